// round 6
// baseline (speedup 1.0000x reference)
#include <cuda_runtime.h>
#include <cuda_fp16.h>

// Problem constants (fixed by the reference: B=2, C=8, L=256, D=128)
#define B_  2
#define C_  8
#define L_  256
#define D_  128
#define TILE 32          // 32x32 output tile per block
#define THREADS 256      // 16 (ti: row-pairs) x 16 (tj: col-pairs), 2x2 out each

__device__ __forceinline__ __half2 tanh_h2(__half2 x) {
    unsigned xi = *reinterpret_cast<unsigned*>(&x);
    unsigned yi;
    asm("tanh.approx.f16x2 %0, %1;" : "=r"(yi) : "r"(xi));
    return *reinterpret_cast<__half2*>(&yi);
}

// Exact f16 -> (f32 value * 2^-112) via bit ops (no XU-pipe CVT).
// Sign preserved; f16 subnormals map to correct f32 subnormals.
// The 2^112 factor is pre-multiplied into v.
__device__ __forceinline__ float h_lo_raw(unsigned u) {
    unsigned t;
    asm("mul.lo.u32 %0, %1, 8192;" : "=r"(t) : "r"(u));    // u<<13 on fma pipe
    return __uint_as_float((t & 0x0FFFE000u) | ((u << 16) & 0x80000000u));
}
__device__ __forceinline__ float h_hi_raw(unsigned u) {
    unsigned a = __umulhi(u, 1u << 29);                    // u>>3 on fma pipe
    return __uint_as_float((a & 0x0FFFE000u) | (u & 0x80000000u));
}

__device__ __forceinline__ __half2 splat_lo(__half2 x) { return __half2half2(__low2half(x)); }
__device__ __forceinline__ __half2 splat_hi(__half2 x) { return __half2half2(__high2half(x)); }

// smem: paired-(d,row) half words.
// Word w[d2*16 + rp] (uint2) holds halves:
//   .x = { h(2d2,   2rp), h(2d2,   2rp+1) }
//   .y = { h(2d2+1, 2rp), h(2d2+1, 2rp+1) }
__global__ __launch_bounds__(THREADS)
void Add_Attn_Layer_59055800320841_kernel(const float* __restrict__ S,
                                          const float* __restrict__ E,
                                          const float* __restrict__ V,
                                          float* __restrict__ out) {
    __shared__ __half sP[D_ * TILE];      // 8 KB
    __shared__ __half eP[D_ * TILE];      // 8 KB
    __shared__ float  vv[D_];             // v * 2^112

    const int bc = blockIdx.z;            // b*C + c   (0..15)
    const int i0 = blockIdx.y * TILE;
    const int j0 = blockIdx.x * TILE;

    const float* Sbase = S + (size_t)bc * L_ * D_ + (size_t)i0 * D_;
    const float* Ebase = E + (size_t)bc * L_ * D_ + (size_t)j0 * D_;

    const int tid = threadIdx.x;

    if (tid < D_) vv[tid] = V[tid] * 0x1p112f;   // exact scale (power of 2)

    // Load + transpose + fp32->fp16 into the paired layout.
    // Lanes take consecutive rows at the same d4 -> coalesced 16B gmem loads.
    #pragma unroll
    for (int idx = tid; idx < TILE * (D_ / 4); idx += THREADS) {
        const int row = idx & (TILE - 1);
        const int d4  = idx >> 5;                 // d = 4*d4 + q
        const float4 sv = *reinterpret_cast<const float4*>(Sbase + row * D_ + d4 * 4);
        const float4 ev = *reinterpret_cast<const float4*>(Ebase + row * D_ + d4 * 4);
        const int rp = row >> 1, rb = row & 1;
        #pragma unroll
        for (int q = 0; q < 4; q++) {
            const int d = 4 * d4 + q;
            const int off = ((d >> 1) * 16 + rp) * 4 + (d & 1) * 2 + rb;
            const float fs = (q == 0) ? sv.x : (q == 1) ? sv.y : (q == 2) ? sv.z : sv.w;
            const float fe = (q == 0) ? ev.x : (q == 1) ? ev.y : (q == 2) ? ev.z : ev.w;
            sP[off] = __float2half_rn(fs);
            eP[off] = __float2half_rn(fe);
        }
    }
    __syncthreads();

    // Thread -> 2 rows x 2 cols
    const int tj = tid & 15;
    const int ti = tid >> 4;

    float a00 = 0.f, a01 = 0.f, a10 = 0.f, a11 = 0.f;

    const uint2* sW = reinterpret_cast<const uint2*>(sP);
    const uint2* eW = reinterpret_cast<const uint2*>(eP);
    const float2* vv2 = reinterpret_cast<const float2*>(vv);

    #pragma unroll 4
    for (int d2 = 0; d2 < D_ / 2; d2++) {
        const uint2  su = sW[d2 * 16 + ti];
        const uint2  eu = eW[d2 * 16 + tj];
        const float2 v2 = vv2[d2];

        // ---- d = 2*d2 ----
        {
            const __half2 s2 = *reinterpret_cast<const __half2*>(&su.x);
            const __half2 e2 = *reinterpret_cast<const __half2*>(&eu.x);
            const __half2 t0h = tanh_h2(__hadd2(splat_lo(s2), e2)); // (r0c0, r0c1)
            const __half2 t1h = tanh_h2(__hadd2(splat_hi(s2), e2)); // (r1c0, r1c1)
            const unsigned t0 = *reinterpret_cast<const unsigned*>(&t0h);
            const unsigned t1 = *reinterpret_cast<const unsigned*>(&t1h);
            a00 = fmaf(v2.x, h_lo_raw(t0), a00);
            a01 = fmaf(v2.x, h_hi_raw(t0), a01);
            a10 = fmaf(v2.x, h_lo_raw(t1), a10);
            a11 = fmaf(v2.x, h_hi_raw(t1), a11);
        }
        // ---- d = 2*d2+1 ----
        {
            const __half2 s2 = *reinterpret_cast<const __half2*>(&su.y);
            const __half2 e2 = *reinterpret_cast<const __half2*>(&eu.y);
            const __half2 t0h = tanh_h2(__hadd2(splat_lo(s2), e2));
            const __half2 t1h = tanh_h2(__hadd2(splat_hi(s2), e2));
            const unsigned t0 = *reinterpret_cast<const unsigned*>(&t0h);
            const unsigned t1 = *reinterpret_cast<const unsigned*>(&t1h);
            a00 = fmaf(v2.y, h_lo_raw(t0), a00);
            a01 = fmaf(v2.y, h_hi_raw(t0), a01);
            a10 = fmaf(v2.y, h_lo_raw(t1), a10);
            a11 = fmaf(v2.y, h_hi_raw(t1), a11);
        }
    }

    // out[b][i][j][c], c fastest; bc = b*C + c
    const int b = bc >> 3;
    const int c = bc & 7;
    const int i = i0 + 2 * ti;
    const int j = j0 + 2 * tj;
    float* o = out + (((size_t)b * L_ + i) * L_ + j) * C_ + c;
    const size_t row_stride = (size_t)L_ * C_;   // i -> i+1
    o[0]               = a00;
    o[C_]              = a01;
    o[row_stride]      = a10;
    o[row_stride + C_] = a11;
}

extern "C" void kernel_launch(void* const* d_in, const int* in_sizes, int n_in,
                              void* d_out, int out_size) {
    (void)in_sizes; (void)n_in; (void)out_size;
    const float* S = (const float*)d_in[0];   // start_hidden [B,C,L,D]
    const float* E = (const float*)d_in[1];   // end_hidden   [B,C,L,D]
    const float* V = (const float*)d_in[2];   // v [D]
    float* out = (float*)d_out;               // [B,L,L,C] float32

    dim3 grid(L_ / TILE, L_ / TILE, B_ * C_); // (8, 8, 16) = 1024 blocks
    Add_Attn_Layer_59055800320841_kernel<<<grid, THREADS>>>(S, E, V, out);
}

// round 8
// speedup vs baseline: 1.1109x; 1.1109x over previous
#include <cuda_runtime.h>
#include <cuda_fp16.h>

// Problem constants (fixed by the reference: B=2, C=8, L=256, D=128)
#define B_  2
#define C_  8
#define L_  256
#define D_  128
#define TILE 32          // 32x32 output tile per block
#define THREADS 256      // 16 (ti: row-pairs) x 16 (tj: col-pairs), 2x2 out each
#define GROUP_D 8        // d-values per fp16 accumulation group (4 d2 steps)

__device__ __forceinline__ __half2 tanh_h2(__half2 x) {
    unsigned xi = *reinterpret_cast<unsigned*>(&x);
    unsigned yi;
    asm("tanh.approx.f16x2 %0, %1;" : "=r"(yi) : "r"(xi));
    return *reinterpret_cast<__half2*>(&yi);
}

// Exact f16 -> (f16 value * 2^-112) as f32, via bit ops (no XU-pipe CVT).
// f16 exponent field is left unrebased in the f32 exponent slot:
// 2^(E-127) vs 2^(E-15) => factor 2^-112. Subnormals map consistently.
__device__ __forceinline__ float h_lo_raw(unsigned u) {
    return __uint_as_float(((u << 13) & 0x0FFFE000u) | ((u << 16) & 0x80000000u));
}
__device__ __forceinline__ float h_hi_raw(unsigned u) {
    return __uint_as_float(((u >> 3) & 0x0FFFE000u) | (u & 0x80000000u));
}

__device__ __forceinline__ __half2 splat_lo(__half2 x) { return __half2half2(__low2half(x)); }
__device__ __forceinline__ __half2 splat_hi(__half2 x) { return __half2half2(__high2half(x)); }

// Flush multiplier: undo the 2^-112 of the bit-convert and the 256x on v.
// 2^112 / 256 = 2^104.
#define UNSCALE 0x1p104f

// smem: paired-(d,row) half words.
// Word w[d2*16 + rp] (uint2) holds halves:
//   .x = { h(2d2,   2rp), h(2d2,   2rp+1) }
//   .y = { h(2d2+1, 2rp), h(2d2+1, 2rp+1) }
__global__ __launch_bounds__(THREADS)
void Add_Attn_Layer_59055800320841_kernel(const float* __restrict__ S,
                                          const float* __restrict__ E,
                                          const float* __restrict__ V,
                                          float* __restrict__ out) {
    __shared__ __half  sP[D_ * TILE];     // 8 KB
    __shared__ __half  eP[D_ * TILE];     // 8 KB
    __shared__ __half2 vh2[D_];           // (v_d*256, v_d*256)  512 B

    const int bc = blockIdx.z;            // b*C + c   (0..15)
    const int i0 = blockIdx.y * TILE;
    const int j0 = blockIdx.x * TILE;

    const float* Sbase = S + (size_t)bc * L_ * D_ + (size_t)i0 * D_;
    const float* Ebase = E + (size_t)bc * L_ * D_ + (size_t)j0 * D_;

    const int tid = threadIdx.x;

    if (tid < D_) {
        const __half vs = __float2half_rn(V[tid] * 256.0f);
        vh2[tid] = __half2half2(vs);
    }

    // Load + transpose + fp32->fp16 into the paired layout.
    // Lanes take consecutive rows at the same d4 -> coalesced 16B gmem loads.
    #pragma unroll
    for (int idx = tid; idx < TILE * (D_ / 4); idx += THREADS) {
        const int row = idx & (TILE - 1);
        const int d4  = idx >> 5;                 // d = 4*d4 + q
        const float4 sv = *reinterpret_cast<const float4*>(Sbase + row * D_ + d4 * 4);
        const float4 ev = *reinterpret_cast<const float4*>(Ebase + row * D_ + d4 * 4);
        const int rp = row >> 1, rb = row & 1;
        #pragma unroll
        for (int q = 0; q < 4; q++) {
            const int d = 4 * d4 + q;
            const int off = ((d >> 1) * 16 + rp) * 4 + (d & 1) * 2 + rb;
            const float fs = (q == 0) ? sv.x : (q == 1) ? sv.y : (q == 2) ? sv.z : sv.w;
            const float fe = (q == 0) ? ev.x : (q == 1) ? ev.y : (q == 2) ? ev.z : ev.w;
            sP[off] = __float2half_rn(fs);
            eP[off] = __float2half_rn(fe);
        }
    }
    __syncthreads();

    // Thread -> 2 rows x 2 cols
    const int tj = tid & 15;
    const int ti = tid >> 4;

    float a00 = 0.f, a01 = 0.f, a10 = 0.f, a11 = 0.f;

    const uint2* sW = reinterpret_cast<const uint2*>(sP);
    const uint2* eW = reinterpret_cast<const uint2*>(eP);

    #pragma unroll 2
    for (int g = 0; g < D_ / GROUP_D; g++) {          // 16 groups
        __half2 h0 = __half2half2(__ushort_as_half(0));  // row0: (c0, c1)
        __half2 h1 = __half2half2(__ushort_as_half(0));  // row1: (c0, c1)

        #pragma unroll
        for (int k = 0; k < GROUP_D / 2; k++) {       // 4 d2 steps
            const int d2 = g * (GROUP_D / 2) + k;
            const uint2 su = sW[d2 * 16 + ti];
            const uint2 eu = eW[d2 * 16 + tj];

            // ---- d = 2*d2 ----
            {
                const __half2 s2 = *reinterpret_cast<const __half2*>(&su.x);
                const __half2 e2 = *reinterpret_cast<const __half2*>(&eu.x);
                const __half2 vh = vh2[2 * d2];
                const __half2 t0 = tanh_h2(__hadd2(splat_lo(s2), e2));
                const __half2 t1 = tanh_h2(__hadd2(splat_hi(s2), e2));
                h0 = __hfma2(vh, t0, h0);
                h1 = __hfma2(vh, t1, h1);
            }
            // ---- d = 2*d2+1 ----
            {
                const __half2 s2 = *reinterpret_cast<const __half2*>(&su.y);
                const __half2 e2 = *reinterpret_cast<const __half2*>(&eu.y);
                const __half2 vh = vh2[2 * d2 + 1];
                const __half2 t0 = tanh_h2(__hadd2(splat_lo(s2), e2));
                const __half2 t1 = tanh_h2(__hadd2(splat_hi(s2), e2));
                h0 = __hfma2(vh, t0, h0);
                h1 = __hfma2(vh, t1, h1);
            }
        }

        // Flush group sums to f32 (bit-convert + FFMA-immediate rescale).
        const unsigned u0 = *reinterpret_cast<const unsigned*>(&h0);
        const unsigned u1 = *reinterpret_cast<const unsigned*>(&h1);
        a00 = fmaf(UNSCALE, h_lo_raw(u0), a00);
        a01 = fmaf(UNSCALE, h_hi_raw(u0), a01);
        a10 = fmaf(UNSCALE, h_lo_raw(u1), a10);
        a11 = fmaf(UNSCALE, h_hi_raw(u1), a11);
    }

    // out[b][i][j][c], c fastest; bc = b*C + c
    const int b = bc >> 3;
    const int c = bc & 7;
    const int i = i0 + 2 * ti;
    const int j = j0 + 2 * tj;
    float* o = out + (((size_t)b * L_ + i) * L_ + j) * C_ + c;
    const size_t row_stride = (size_t)L_ * C_;   // i -> i+1
    o[0]               = a00;
    o[C_]              = a01;
    o[row_stride]      = a10;
    o[row_stride + C_] = a11;
}

extern "C" void kernel_launch(void* const* d_in, const int* in_sizes, int n_in,
                              void* d_out, int out_size) {
    (void)in_sizes; (void)n_in; (void)out_size;
    const float* S = (const float*)d_in[0];   // start_hidden [B,C,L,D]
    const float* E = (const float*)d_in[1];   // end_hidden   [B,C,L,D]
    const float* V = (const float*)d_in[2];   // v [D]
    float* out = (float*)d_out;               // [B,L,L,C] float32

    dim3 grid(L_ / TILE, L_ / TILE, B_ * C_); // (8, 8, 16) = 1024 blocks
    Add_Attn_Layer_59055800320841_kernel<<<grid, THREADS>>>(S, E, V, out);
}